// round 8
// baseline (speedup 1.0000x reference)
#include <cuda_runtime.h>
#include <cuda_bf16.h>
#include <math.h>

// ConvLSTM via mma.sync m16n8k16 bf16, 3-term hi/lo split.
// Round 8: 2-stage smem pipeline. CTA = 256 pixels (4 rows x 64) x 64 oc,
// 8 warps, 2 m-tiles/warp. cp.async prefetch of kb+1 overlaps MMA of kb.
// Weights prepacked in exact smem layout -> contiguous coalesced staging.
// x: (8,16,64,64,64) f32, Wk: (256,128,3,3) f32
// out: [hid | cell], each 8*64*64*64 f32 (NCHW).

#define HW 64

__device__ __nv_bfloat16 g_xs[2][8][16][HW][HW][64];   // x channel-last hi/lo
__device__ __nv_bfloat16 g_hs[2][2][8][HW][HW][64];    // [parity][split] h hi/lo
__device__ __nv_bfloat16 g_wpk[4][8][27648];           // prepacked weights per (hcg,kb)
__device__ __align__(16) __nv_bfloat16 g_zero16[8] = {};

// smem layout per stage (bf16 elems):
//   input  [sp2][sy 6][sx 66][24]  = 19008
//   weights[sp2][tap 9][ocl 64][24] = 27648
#define SIN_ELEMS 19008
#define SIN_SP    (6 * 66 * 24)
#define SW_SP     (9 * 64 * 24)
#define STAGE_ELEMS (19008 + 27648)
#define STAGE_BYTES (STAGE_ELEMS * 2)
#define SMEM_BYTES  (2 * STAGE_BYTES)

// ---------------- prep kernels ----------------

__global__ void prep_x(const float* __restrict__ x)
{
    __shared__ float tile[64][65];
    int y  = blockIdx.x & 63;
    int bt = blockIdx.x >> 6;               // b*16 + t
    const float* src = x + (size_t)bt * 64 * 4096 + y * 64;
    for (int i = threadIdx.x; i < 64 * 64; i += 256) {
        int ic = i >> 6, xx = i & 63;
        tile[ic][xx] = src[ic * 4096 + xx];
    }
    __syncthreads();
    int b = bt >> 4, t = bt & 15;
    for (int i = threadIdx.x; i < 64 * 64; i += 256) {
        int xx = i >> 6, ic = i & 63;
        float v = tile[ic][xx];
        __nv_bfloat16 hi = __float2bfloat16(v);
        g_xs[0][b][t][y][xx][ic] = hi;
        g_xs[1][b][t][y][xx][ic] = __float2bfloat16(v - __bfloat162float(hi));
    }
}

// Prepack weights into the exact smem layout for (hcg, kb):
//   [sp][tap][ocl][icp(24, 16 valid)]  with oc = (ocl>>4)*64 + hcg*16 + (ocl&15)
__global__ void prep_wpk(const float* __restrict__ Wk)
{
    int i = blockIdx.x * blockDim.x + threadIdx.x;  // over 4*8*27648
    if (i >= 4 * 8 * 27648) return;
    int e   = i % 27648;
    int kb  = (i / 27648) & 7;
    int hcg = i / (27648 * 8);
    int sp  = e / 13824;
    int r   = e - sp * 13824;
    int tap = r / (64 * 24);
    int q   = r - tap * (64 * 24);
    int ocl = q / 24;
    int icp = q - ocl * 24;
    __nv_bfloat16 out = __float2bfloat16(0.f);
    if (icp < 16) {
        int oc  = (ocl >> 4) * 64 + hcg * 16 + (ocl & 15);
        int cin = kb * 16 + icp;
        float v = Wk[(size_t)(oc * 128 + cin) * 9 + tap];
        __nv_bfloat16 hi = __float2bfloat16(v);
        out = sp ? __float2bfloat16(v - __bfloat162float(hi)) : hi;
    }
    g_wpk[hcg][kb][e] = out;
}

// ---------------- helpers ----------------

__device__ __forceinline__ void ldsm4(unsigned &r0, unsigned &r1,
                                      unsigned &r2, unsigned &r3, unsigned a)
{
    asm volatile("ldmatrix.sync.aligned.m8n8.x4.shared.b16 {%0,%1,%2,%3}, [%4];"
                 : "=r"(r0), "=r"(r1), "=r"(r2), "=r"(r3) : "r"(a));
}

__device__ __forceinline__ void mma_bf16(float* c, const unsigned* a, const unsigned* b)
{
    asm volatile("mma.sync.aligned.m16n8k16.row.col.f32.bf16.bf16.f32 "
                 "{%0,%1,%2,%3},{%4,%5,%6,%7},{%8,%9},{%0,%1,%2,%3};"
                 : "+f"(c[0]), "+f"(c[1]), "+f"(c[2]), "+f"(c[3])
                 : "r"(a[0]), "r"(a[1]), "r"(a[2]), "r"(a[3]),
                   "r"(b[0]), "r"(b[1]));
}

__device__ __forceinline__ void cpasync16(unsigned dst, const void* src)
{
    asm volatile("cp.async.cg.shared.global [%0], [%1], 16;"
                 :: "r"(dst), "l"(src) : "memory");
}

__global__ __launch_bounds__(256, 1)
void convlstm_mma(float* __restrict__ hid_out, float* __restrict__ cell_io,
                  int t, int last)
{
    extern __shared__ __nv_bfloat16 smem[];

    const int tid  = threadIdx.x;
    const int w    = tid >> 5;            // 0..7
    const int lane = tid & 31;
    const int y0   = blockIdx.x * 4;      // 4 output rows per block
    const int hcg  = blockIdx.y;          // hidden-ch group (16 each)
    const int b    = blockIdx.z;

    const int par_in  = t & 1;
    const int par_out = (t + 1) & 1;

    const unsigned sBase = (unsigned)__cvta_generic_to_shared(smem);

    // lane-invariant ldmatrix offsets (relative to stage base)
    const int t4 = lane >> 3, r8 = lane & 7;
    const int prA = ((t4 & 1) << 3) + r8;
    const int k8A = t4 >> 1;
    unsigned laneA[2];
#pragma unroll
    for (int mt = 0; mt < 2; mt++) {
        const int p0  = w * 32 + mt * 16 + prA;   // 0..255
        const int pyA = p0 >> 6;                  // 0..3 local row
        const int pxA = p0 & 63;
        laneA[mt] = (unsigned)((pyA * 66 + pxA) * 24 + 8 * k8A) * 2u;
    }
    const int hi8 = (t4 >= 2) ? 8 : 0;
    const unsigned laneB = (unsigned)(((hi8 + r8) * 24) + 8 * (t4 & 1)) * 2u;

    float acc[2][8][4];
#pragma unroll
    for (int m = 0; m < 2; m++)
#pragma unroll
        for (int i = 0; i < 8; i++)
#pragma unroll
            for (int j = 0; j < 4; j++) acc[m][i][j] = 0.f;

    const int nkb = (t == 0) ? 4 : 8;

    // ---- stage loader (cp.async; caller commits) ----
    auto load_stage = [&](int kb, int st) {
        const unsigned sIn = sBase + (unsigned)st * STAGE_BYTES;
        const unsigned sW  = sIn + SIN_ELEMS * 2;
        // input: 2 sp x 6 rows (halo) x 66 x 2 halves of 8 ic
        for (int c = tid; c < 1584; c += 256) {
            int sp   = c / 792;
            int idx  = c - sp * 792;
            int pix  = idx >> 1, half = idx & 1;
            int sy   = pix / 66, sx = pix - sy * 66;
            int gy   = y0 - 1 + sy, gx = sx - 1;
            const void* src = g_zero16;
            if ((unsigned)gy < 64u && (unsigned)gx < 64u)
                src = (kb < 4)
                    ? (const void*)&g_xs[sp][b][t][gy][gx][kb * 16 + half * 8]
                    : (const void*)&g_hs[par_in][sp][b][gy][gx][(kb - 4) * 16 + half * 8];
            unsigned dst = sIn + (unsigned)(((sp * 6 + sy) * 66 + sx) * 24 + half * 8) * 2u;
            cpasync16(dst, src);
        }
        // weights: contiguous prepacked block, 27648 elems = 3456 x 16B
        const char* wsrc = (const char*)g_wpk[hcg][kb];
        for (int i = tid; i < 3456; i += 256)
            cpasync16(sW + (unsigned)i * 16u, wsrc + (size_t)i * 16);
    };

    load_stage(0, 0);
    asm volatile("cp.async.commit_group;" ::: "memory");

    for (int kb = 0; kb < nkb; kb++) {
        const int st = kb & 1;
        if (kb + 1 < nkb) {
            load_stage(kb + 1, st ^ 1);
            asm volatile("cp.async.commit_group;" ::: "memory");
            asm volatile("cp.async.wait_group 1;" ::: "memory");
        } else {
            asm volatile("cp.async.wait_group 0;" ::: "memory");
        }
        __syncthreads();

        const unsigned sIn = sBase + (unsigned)st * STAGE_BYTES;
        const unsigned sW  = sIn + SIN_ELEMS * 2;

#pragma unroll 1
        for (int tap = 0; tap < 9; tap++) {
            const int dyp = tap / 3, dxp = tap - dyp * 3;
            const unsigned aoff = (unsigned)((dyp * 66 + dxp) * 24) * 2u;

            unsigned a[2][2][4];   // [mt][sp][frag]
#pragma unroll
            for (int mt = 0; mt < 2; mt++) {
                ldsm4(a[mt][0][0], a[mt][0][1], a[mt][0][2], a[mt][0][3],
                      sIn + aoff + laneA[mt]);
                ldsm4(a[mt][1][0], a[mt][1][1], a[mt][1][2], a[mt][1][3],
                      sIn + (unsigned)(SIN_SP * 2) + aoff + laneA[mt]);
            }

            unsigned bf[2][8][2];
#pragma unroll
            for (int sp = 0; sp < 2; sp++) {
                unsigned base = sW + (unsigned)(sp * SW_SP + tap * 64 * 24) * 2u + laneB;
#pragma unroll
                for (int j = 0; j < 4; j++) {
                    ldsm4(bf[sp][2 * j][0], bf[sp][2 * j][1],
                          bf[sp][2 * j + 1][0], bf[sp][2 * j + 1][1],
                          base + (unsigned)(16 * j * 24) * 2u);
                }
            }
#pragma unroll
            for (int nf = 0; nf < 8; nf++) {
#pragma unroll
                for (int mt = 0; mt < 2; mt++) {
                    mma_bf16(acc[mt][nf], a[mt][0], bf[0][nf]);   // hi*hi
                    mma_bf16(acc[mt][nf], a[mt][0], bf[1][nf]);   // hi*w_lo
                    mma_bf16(acc[mt][nf], a[mt][1], bf[0][nf]);   // lo*w_hi
                }
            }
        }
        __syncthreads();   // all warps done reading stage st before it is reloaded
    }

    // ---- fused LSTM epilogue ----
    const int c0    = (lane & 3) * 2;
    const int rbase = lane >> 2;
#pragma unroll
    for (int mt = 0; mt < 2; mt++) {
#pragma unroll
        for (int rr = 0; rr < 2; rr++) {
            const int pe = w * 32 + mt * 16 + rbase + 8 * rr;
            const int y  = y0 + (pe >> 6);
            const int x  = pe & 63;
#pragma unroll
            for (int q = 0; q < 4; q++) {
                const int hcl  = c0 + (q & 1) + ((q >> 1) << 3);
                const int off  = (hcl >= 8) ? 1 : 0;
                const int cidx = (hcl & 7) - c0 + rr * 2;
                float vi = acc[mt][0 + off][cidx];
                float vf = acc[mt][2 + off][cidx];
                float vo = acc[mt][4 + off][cidx];
                float vg = acc[mt][6 + off][cidx];
                float iv = 1.f / (1.f + __expf(-vi));
                float fv = 1.f / (1.f + __expf(-vf));
                float ov = 1.f / (1.f + __expf(-vo));
                float gv = tanhf(vg);
                const int hc = hcg * 16 + hcl;
                const size_t addr = (((size_t)b * 64 + hc) * 64 + y) * 64 + x;
                float cold = (t == 0) ? 0.f : cell_io[addr];
                float cnew = fv * cold + iv * gv;
                cell_io[addr] = cnew;
                float hval = ov * tanhf(cnew);
                if (last) {
                    hid_out[addr] = hval;
                } else {
                    __nv_bfloat16 hh = __float2bfloat16(hval);
                    g_hs[par_out][0][b][y][x][hc] = hh;
                    g_hs[par_out][1][b][y][x][hc] =
                        __float2bfloat16(hval - __bfloat162float(hh));
                }
            }
        }
    }
}

extern "C" void kernel_launch(void* const* d_in, const int* in_sizes, int n_in,
                              void* d_out, int out_size)
{
    const float* x  = (const float*)d_in[0];
    const float* Wk = (const float*)d_in[1];
    float* out  = (float*)d_out;
    float* hid  = out;
    float* cell = out + out_size / 2;

    cudaFuncSetAttribute(convlstm_mma,
                         cudaFuncAttributeMaxDynamicSharedMemorySize, SMEM_BYTES);

    prep_wpk<<<(4 * 8 * 27648 + 255) / 256, 256>>>(Wk);
    prep_x<<<8 * 16 * 64, 256>>>(x);

    dim3 grid(16, 4, 8), blk(256);
    for (int t = 0; t < 16; t++)
        convlstm_mma<<<grid, blk, SMEM_BYTES>>>(hid, cell, t, t == 15 ? 1 : 0);
}

// round 9
// speedup vs baseline: 1.8035x; 1.8035x over previous
#include <cuda_runtime.h>
#include <cuda_bf16.h>
#include <math.h>

// ConvLSTM via mma.sync m16n8k16 bf16, 3-term hi/lo split.
// Round 9: R5 geometry (CTA = 256 px (4 rows) x 64 oc, 8 warps,
// 2 m-tiles/warp => 1.0 LDSM-wf/MMA) but register-capped to 128 via
// launch_bounds(256,2) + two-phase B-fragment loading, so 2 CTAs/SM
// (16 warps/SM) restore the inter-CTA staging/compute overlap that
// made R4 fastest. Weights prepacked in exact smem layout.
// x: (8,16,64,64,64) f32, Wk: (256,128,3,3) f32
// out: [hid | cell], each 8*64*64*64 f32 (NCHW).

#define HW 64

__device__ __nv_bfloat16 g_xs[2][8][16][HW][HW][64];   // x channel-last hi/lo
__device__ __nv_bfloat16 g_hs[2][2][8][HW][HW][64];    // [parity][split] h hi/lo
__device__ __nv_bfloat16 g_wpk[4][8][27648];           // prepacked weights (hcg,kb)
__device__ __align__(16) __nv_bfloat16 g_zero16[8] = {};

// smem (bf16 elems): s_in [2][6][66][24] = 19008 ; s_w [2][9][64][24] = 27648
#define SIN_ELEMS 19008
#define SIN_SP    (6 * 66 * 24)
#define SW_SP     (9 * 64 * 24)
#define SMEM_BYTES ((19008 + 27648) * 2)   // 93312 B -> 2 CTAs/SM

// ---------------- prep kernels ----------------

__global__ void prep_x(const float* __restrict__ x)
{
    __shared__ float tile[64][65];
    int y  = blockIdx.x & 63;
    int bt = blockIdx.x >> 6;               // b*16 + t
    const float* src = x + (size_t)bt * 64 * 4096 + y * 64;
    for (int i = threadIdx.x; i < 64 * 64; i += 256) {
        int ic = i >> 6, xx = i & 63;
        tile[ic][xx] = src[ic * 4096 + xx];
    }
    __syncthreads();
    int b = bt >> 4, t = bt & 15;
    for (int i = threadIdx.x; i < 64 * 64; i += 256) {
        int xx = i >> 6, ic = i & 63;
        float v = tile[ic][xx];
        __nv_bfloat16 hi = __float2bfloat16(v);
        g_xs[0][b][t][y][xx][ic] = hi;
        g_xs[1][b][t][y][xx][ic] = __float2bfloat16(v - __bfloat162float(hi));
    }
}

// Prepack weights in exact smem layout for (hcg,kb): [sp][tap][ocl][24]
__global__ void prep_wpk(const float* __restrict__ Wk)
{
    int i = blockIdx.x * blockDim.x + threadIdx.x;  // over 4*8*27648
    if (i >= 4 * 8 * 27648) return;
    int e   = i % 27648;
    int kb  = (i / 27648) & 7;
    int hcg = i / (27648 * 8);
    int sp  = e / 13824;
    int r   = e - sp * 13824;
    int tap = r / (64 * 24);
    int q   = r - tap * (64 * 24);
    int ocl = q / 24;
    int icp = q - ocl * 24;
    __nv_bfloat16 out = __float2bfloat16(0.f);
    if (icp < 16) {
        int oc  = (ocl >> 4) * 64 + hcg * 16 + (ocl & 15);
        int cin = kb * 16 + icp;
        float v = Wk[(size_t)(oc * 128 + cin) * 9 + tap];
        __nv_bfloat16 hi = __float2bfloat16(v);
        out = sp ? __float2bfloat16(v - __bfloat162float(hi)) : hi;
    }
    g_wpk[hcg][kb][e] = out;
}

// ---------------- helpers ----------------

__device__ __forceinline__ void ldsm4(unsigned &r0, unsigned &r1,
                                      unsigned &r2, unsigned &r3, unsigned a)
{
    asm volatile("ldmatrix.sync.aligned.m8n8.x4.shared.b16 {%0,%1,%2,%3}, [%4];"
                 : "=r"(r0), "=r"(r1), "=r"(r2), "=r"(r3) : "r"(a));
}

__device__ __forceinline__ void mma_bf16(float* c, const unsigned* a, const unsigned* b)
{
    asm volatile("mma.sync.aligned.m16n8k16.row.col.f32.bf16.bf16.f32 "
                 "{%0,%1,%2,%3},{%4,%5,%6,%7},{%8,%9},{%0,%1,%2,%3};"
                 : "+f"(c[0]), "+f"(c[1]), "+f"(c[2]), "+f"(c[3])
                 : "r"(a[0]), "r"(a[1]), "r"(a[2]), "r"(a[3]),
                   "r"(b[0]), "r"(b[1]));
}

__device__ __forceinline__ void cpasync16(unsigned dst, const void* src)
{
    asm volatile("cp.async.cg.shared.global [%0], [%1], 16;"
                 :: "r"(dst), "l"(src) : "memory");
}

__global__ __launch_bounds__(256, 2)
void convlstm_mma(float* __restrict__ hid_out, float* __restrict__ cell_io,
                  int t, int last)
{
    extern __shared__ __nv_bfloat16 smem[];
    __nv_bfloat16* s_in = smem;               // [sp][sy 6][sx 66][24]
    __nv_bfloat16* s_w  = smem + SIN_ELEMS;   // [sp][tap 9][ocl 64][24]

    const int tid  = threadIdx.x;
    const int w    = tid >> 5;            // 0..7
    const int lane = tid & 31;
    const int y0   = blockIdx.x * 4;      // 4 output rows per block
    const int hcg  = blockIdx.y;
    const int b    = blockIdx.z;

    const int par_in  = t & 1;
    const int par_out = (t + 1) & 1;

    const unsigned sIn = (unsigned)__cvta_generic_to_shared(s_in);
    const unsigned sW  = (unsigned)__cvta_generic_to_shared(s_w);

    // lane-invariant ldmatrix offsets
    const int t4 = lane >> 3, r8 = lane & 7;
    const int prA = ((t4 & 1) << 3) + r8;
    const int k8A = t4 >> 1;
    unsigned laneA[2];
#pragma unroll
    for (int mt = 0; mt < 2; mt++) {
        const int p0  = w * 32 + mt * 16 + prA;   // 0..255
        const int pyA = p0 >> 6;                  // local row 0..3
        const int pxA = p0 & 63;
        laneA[mt] = (unsigned)((pyA * 66 + pxA) * 24 + 8 * k8A) * 2u;
    }
    const int hi8 = (t4 >= 2) ? 8 : 0;
    const unsigned laneB = (unsigned)(((hi8 + r8) * 24) + 8 * (t4 & 1)) * 2u;

    float acc[2][8][4];
#pragma unroll
    for (int m = 0; m < 2; m++)
#pragma unroll
        for (int i = 0; i < 8; i++)
#pragma unroll
            for (int j = 0; j < 4; j++) acc[m][i][j] = 0.f;

    const int nkb = (t == 0) ? 4 : 8;

    for (int kb = 0; kb < nkb; kb++) {
        __syncthreads();   // prior kb's ldsm reads complete

        // ---- stage input via cp.async: 2sp x 6 rows (halo) x 66 x 2 halves
        for (int c = tid; c < 1584; c += 256) {
            int sp   = c / 792;
            int idx  = c - sp * 792;
            int pix  = idx >> 1, half = idx & 1;
            int sy   = pix / 66, sx = pix - sy * 66;
            int gy   = y0 - 1 + sy, gx = sx - 1;
            const void* src = g_zero16;
            if ((unsigned)gy < 64u && (unsigned)gx < 64u)
                src = (kb < 4)
                    ? (const void*)&g_xs[sp][b][t][gy][gx][kb * 16 + half * 8]
                    : (const void*)&g_hs[par_in][sp][b][gy][gx][(kb - 4) * 16 + half * 8];
            unsigned dst = sIn + (unsigned)(((sp * 6 + sy) * 66 + sx) * 24 + half * 8) * 2u;
            cpasync16(dst, src);
        }
        // ---- stage weights: contiguous prepacked block (3456 x 16B)
        {
            const char* wsrc = (const char*)g_wpk[hcg][kb];
            for (int i = tid; i < 3456; i += 256)
                cpasync16(sW + (unsigned)i * 16u, wsrc + (size_t)i * 16);
        }
        asm volatile("cp.async.commit_group;" ::: "memory");
        asm volatile("cp.async.wait_group 0;" ::: "memory");
        __syncthreads();

#pragma unroll 1
        for (int tap = 0; tap < 9; tap++) {
            const int dyp = tap / 3, dxp = tap - dyp * 3;
            const unsigned aoff = (unsigned)((dyp * 66 + dxp) * 24) * 2u;

            unsigned a[2][2][4];   // [mt][sp][frag]
#pragma unroll
            for (int mt = 0; mt < 2; mt++) {
                ldsm4(a[mt][0][0], a[mt][0][1], a[mt][0][2], a[mt][0][3],
                      sIn + aoff + laneA[mt]);
                ldsm4(a[mt][1][0], a[mt][1][1], a[mt][1][2], a[mt][1][3],
                      sIn + (unsigned)(SIN_SP * 2) + aoff + laneA[mt]);
            }

            unsigned bf[8][2];
            // ---- phase 1: B = w_hi  (terms Ah*Bh, Al*Bh)
            {
                unsigned base = sW + (unsigned)(tap * 64 * 24) * 2u + laneB;
#pragma unroll
                for (int j = 0; j < 4; j++)
                    ldsm4(bf[2 * j][0], bf[2 * j][1],
                          bf[2 * j + 1][0], bf[2 * j + 1][1],
                          base + (unsigned)(16 * j * 24) * 2u);
#pragma unroll
                for (int nf = 0; nf < 8; nf++)
#pragma unroll
                    for (int mt = 0; mt < 2; mt++) {
                        mma_bf16(acc[mt][nf], a[mt][0], bf[nf]);   // hi*w_hi
                        mma_bf16(acc[mt][nf], a[mt][1], bf[nf]);   // lo*w_hi
                    }
            }
            // ---- phase 2: B = w_lo  (term Ah*Bl)
            {
                unsigned base = sW + (unsigned)(SW_SP + tap * 64 * 24) * 2u + laneB;
#pragma unroll
                for (int j = 0; j < 4; j++)
                    ldsm4(bf[2 * j][0], bf[2 * j][1],
                          bf[2 * j + 1][0], bf[2 * j + 1][1],
                          base + (unsigned)(16 * j * 24) * 2u);
#pragma unroll
                for (int nf = 0; nf < 8; nf++)
#pragma unroll
                    for (int mt = 0; mt < 2; mt++)
                        mma_bf16(acc[mt][nf], a[mt][0], bf[nf]);   // hi*w_lo
            }
        }
    }

    // ---- fused LSTM epilogue ----
    const int c0    = (lane & 3) * 2;
    const int rbase = lane >> 2;
#pragma unroll
    for (int mt = 0; mt < 2; mt++) {
#pragma unroll
        for (int rr = 0; rr < 2; rr++) {
            const int pe = w * 32 + mt * 16 + rbase + 8 * rr;
            const int y  = y0 + (pe >> 6);
            const int x  = pe & 63;
#pragma unroll
            for (int q = 0; q < 4; q++) {
                const int hcl  = c0 + (q & 1) + ((q >> 1) << 3);
                const int off  = (hcl >= 8) ? 1 : 0;
                const int cidx = (hcl & 7) - c0 + rr * 2;
                float vi = acc[mt][0 + off][cidx];
                float vf = acc[mt][2 + off][cidx];
                float vo = acc[mt][4 + off][cidx];
                float vg = acc[mt][6 + off][cidx];
                float iv = 1.f / (1.f + __expf(-vi));
                float fv = 1.f / (1.f + __expf(-vf));
                float ov = 1.f / (1.f + __expf(-vo));
                float gv = tanhf(vg);
                const int hc = hcg * 16 + hcl;
                const size_t addr = (((size_t)b * 64 + hc) * 64 + y) * 64 + x;
                float cold = (t == 0) ? 0.f : cell_io[addr];
                float cnew = fv * cold + iv * gv;
                cell_io[addr] = cnew;
                float hval = ov * tanhf(cnew);
                if (last) {
                    hid_out[addr] = hval;
                } else {
                    __nv_bfloat16 hh = __float2bfloat16(hval);
                    g_hs[par_out][0][b][y][x][hc] = hh;
                    g_hs[par_out][1][b][y][x][hc] =
                        __float2bfloat16(hval - __bfloat162float(hh));
                }
            }
        }
    }
}

extern "C" void kernel_launch(void* const* d_in, const int* in_sizes, int n_in,
                              void* d_out, int out_size)
{
    const float* x  = (const float*)d_in[0];
    const float* Wk = (const float*)d_in[1];
    float* out  = (float*)d_out;
    float* hid  = out;
    float* cell = out + out_size / 2;

    cudaFuncSetAttribute(convlstm_mma,
                         cudaFuncAttributeMaxDynamicSharedMemorySize, SMEM_BYTES);

    prep_wpk<<<(4 * 8 * 27648 + 255) / 256, 256>>>(Wk);
    prep_x<<<8 * 16 * 64, 256>>>(x);

    dim3 grid(16, 4, 8), blk(256);
    for (int t = 0; t < 16; t++)
        convlstm_mma<<<grid, blk, SMEM_BYTES>>>(hid, cell, t, t == 15 ? 1 : 0);
}

// round 10
// speedup vs baseline: 1.8228x; 1.0107x over previous
#include <cuda_runtime.h>
#include <cuda_bf16.h>
#include <math.h>

// ConvLSTM via mma.sync m16n8k16 bf16, 3-term hi/lo split.
// Round 10: R9 + (a) compact weight smem layout [sp][ocl][k152] (38.9KB,
// conflict-free 304B row stride), (b) input tile double-buffered and
// prefetched via cp.async commit-groups (wait_group 1) so input staging
// hides behind the tap loop; only weight staging stays exposed.
// smem 114944B -> still 2 CTAs/SM. CTA = 256 px (4 rows x 64) x 64 oc,
// 8 warps, 2 m-tiles/warp, regs capped 128.
// x: (8,16,64,64,64) f32, Wk: (256,128,3,3) f32
// out: [hid | cell], each 8*64*64*64 f32 (NCHW).

#define HW 64

__device__ __nv_bfloat16 g_xs[2][8][16][HW][HW][64];   // x channel-last hi/lo
__device__ __nv_bfloat16 g_hs[2][2][8][HW][HW][64];    // [parity][split] h hi/lo
__device__ __nv_bfloat16 g_wpk[4][8][19456];           // packed weights (hcg,kb)
__device__ __align__(16) __nv_bfloat16 g_zero16[8] = {};

// smem (bf16 elems): in buf = [sp2][sy6][sx66][24] = 19008 (x2 buffers)
//                    w  buf = [sp2][ocl64][152]   = 19456
#define INBUF_ELEMS 19008
#define SIN_SP      (6 * 66 * 24)
#define WBUF_ELEMS  19456
#define W_SP        (64 * 152)
#define SMEM_BYTES  ((2 * 19008 + 19456) * 2)   // 114944

// ---------------- prep kernels ----------------

__global__ void prep_x(const float* __restrict__ x)
{
    __shared__ float tile[64][65];
    int y  = blockIdx.x & 63;
    int bt = blockIdx.x >> 6;               // b*16 + t
    const float* src = x + (size_t)bt * 64 * 4096 + y * 64;
    for (int i = threadIdx.x; i < 64 * 64; i += 256) {
        int ic = i >> 6, xx = i & 63;
        tile[ic][xx] = src[ic * 4096 + xx];
    }
    __syncthreads();
    int b = bt >> 4, t = bt & 15;
    for (int i = threadIdx.x; i < 64 * 64; i += 256) {
        int xx = i >> 6, ic = i & 63;
        float v = tile[ic][xx];
        __nv_bfloat16 hi = __float2bfloat16(v);
        g_xs[0][b][t][y][xx][ic] = hi;
        g_xs[1][b][t][y][xx][ic] = __float2bfloat16(v - __bfloat162float(hi));
    }
}

// Pack weights for (hcg,kb): [sp][ocl 64][k 152], k = tap*16+ic (144 valid).
__global__ void prep_wpk(const float* __restrict__ Wk)
{
    int i = blockIdx.x * blockDim.x + threadIdx.x;  // over 4*8*19456
    if (i >= 4 * 8 * 19456) return;
    int e   = i % 19456;
    int kb  = (i / 19456) & 7;
    int hcg = i / (19456 * 8);
    int sp  = e / 9728;
    int r   = e - sp * 9728;
    int ocl = r / 152;
    int kk  = r - ocl * 152;
    __nv_bfloat16 out = __float2bfloat16(0.f);
    if (kk < 144) {
        int tap = kk >> 4, ic = kk & 15;
        int oc  = (ocl >> 4) * 64 + hcg * 16 + (ocl & 15);
        int cin = kb * 16 + ic;
        float v = Wk[(size_t)(oc * 128 + cin) * 9 + tap];
        __nv_bfloat16 hi = __float2bfloat16(v);
        out = sp ? __float2bfloat16(v - __bfloat162float(hi)) : hi;
    }
    g_wpk[hcg][kb][e] = out;
}

// ---------------- helpers ----------------

__device__ __forceinline__ void ldsm4(unsigned &r0, unsigned &r1,
                                      unsigned &r2, unsigned &r3, unsigned a)
{
    asm volatile("ldmatrix.sync.aligned.m8n8.x4.shared.b16 {%0,%1,%2,%3}, [%4];"
                 : "=r"(r0), "=r"(r1), "=r"(r2), "=r"(r3) : "r"(a));
}

__device__ __forceinline__ void mma_bf16(float* c, const unsigned* a, const unsigned* b)
{
    asm volatile("mma.sync.aligned.m16n8k16.row.col.f32.bf16.bf16.f32 "
                 "{%0,%1,%2,%3},{%4,%5,%6,%7},{%8,%9},{%0,%1,%2,%3};"
                 : "+f"(c[0]), "+f"(c[1]), "+f"(c[2]), "+f"(c[3])
                 : "r"(a[0]), "r"(a[1]), "r"(a[2]), "r"(a[3]),
                   "r"(b[0]), "r"(b[1]));
}

__device__ __forceinline__ void cpasync16(unsigned dst, const void* src)
{
    asm volatile("cp.async.cg.shared.global [%0], [%1], 16;"
                 :: "r"(dst), "l"(src) : "memory");
}

__global__ __launch_bounds__(256, 2)
void convlstm_mma(float* __restrict__ hid_out, float* __restrict__ cell_io,
                  int t, int last)
{
    extern __shared__ __nv_bfloat16 smem[];
    // [buf0 in][buf1 in][weights]
    const unsigned sIn0 = (unsigned)__cvta_generic_to_shared(smem);
    const unsigned sIn1 = sIn0 + INBUF_ELEMS * 2;
    const unsigned sW   = sIn0 + 2 * INBUF_ELEMS * 2;

    const int tid  = threadIdx.x;
    const int w    = tid >> 5;            // 0..7
    const int lane = tid & 31;
    const int y0   = blockIdx.x * 4;      // 4 output rows per block
    const int hcg  = blockIdx.y;
    const int b    = blockIdx.z;

    const int par_in  = t & 1;
    const int par_out = (t + 1) & 1;

    // lane-invariant ldmatrix offsets
    const int t4 = lane >> 3, r8 = lane & 7;
    const int prA = ((t4 & 1) << 3) + r8;
    const int k8A = t4 >> 1;
    unsigned laneA[2];
#pragma unroll
    for (int mt = 0; mt < 2; mt++) {
        const int p0  = w * 32 + mt * 16 + prA;   // 0..255
        const int pyA = p0 >> 6;
        const int pxA = p0 & 63;
        laneA[mt] = (unsigned)((pyA * 66 + pxA) * 24 + 8 * k8A) * 2u;
    }
    const int hi8 = (t4 >= 2) ? 8 : 0;
    const unsigned laneB = (unsigned)((hi8 + r8) * 152 + 8 * (t4 & 1)) * 2u;

    float acc[2][8][4];
#pragma unroll
    for (int m = 0; m < 2; m++)
#pragma unroll
        for (int i = 0; i < 8; i++)
#pragma unroll
            for (int j = 0; j < 4; j++) acc[m][i][j] = 0.f;

    const int nkb = (t == 0) ? 4 : 8;

    // ---- input stage loader (cp.async; caller commits) ----
    auto load_input = [&](int kb, unsigned sIn) {
        for (int c = tid; c < 1584; c += 256) {
            int sp   = c / 792;
            int idx  = c - sp * 792;
            int pix  = idx >> 1, half = idx & 1;
            int sy   = pix / 66, sx = pix - sy * 66;
            int gy   = y0 - 1 + sy, gx = sx - 1;
            const void* src = g_zero16;
            if ((unsigned)gy < 64u && (unsigned)gx < 64u)
                src = (kb < 4)
                    ? (const void*)&g_xs[sp][b][t][gy][gx][kb * 16 + half * 8]
                    : (const void*)&g_hs[par_in][sp][b][gy][gx][(kb - 4) * 16 + half * 8];
            unsigned dst = sIn + (unsigned)(((sp * 6 + sy) * 66 + sx) * 24 + half * 8) * 2u;
            cpasync16(dst, src);
        }
    };

    // prologue: prefetch input(0)
    load_input(0, sIn0);
    asm volatile("cp.async.commit_group;" ::: "memory");

    for (int kb = 0; kb < nkb; kb++) {
        if (kb > 0) __syncthreads();   // all warps done with s_w and old input buf

        // stage weights(kb): contiguous packed block (2432 x 16B)
        {
            const char* wsrc = (const char*)g_wpk[hcg][kb];
            for (int i = tid; i < 2432; i += 256)
                cpasync16(sW + (unsigned)i * 16u, wsrc + (size_t)i * 16);
        }
        asm volatile("cp.async.commit_group;" ::: "memory");

        // prefetch input(kb+1) into the other buffer
        if (kb + 1 < nkb) {
            load_input(kb + 1, (kb + 1) & 1 ? sIn1 : sIn0);
            asm volatile("cp.async.commit_group;" ::: "memory");
            asm volatile("cp.async.wait_group 1;" ::: "memory");
        } else {
            asm volatile("cp.async.wait_group 0;" ::: "memory");
        }
        __syncthreads();

        const unsigned sIn = (kb & 1) ? sIn1 : sIn0;

#pragma unroll 1
        for (int tap = 0; tap < 9; tap++) {
            const int dyp = tap / 3, dxp = tap - dyp * 3;
            const unsigned aoff = (unsigned)((dyp * 66 + dxp) * 24) * 2u;
            const unsigned woff = (unsigned)(tap * 16) * 2u;

            unsigned a[2][2][4];   // [mt][sp][frag]
#pragma unroll
            for (int mt = 0; mt < 2; mt++) {
                ldsm4(a[mt][0][0], a[mt][0][1], a[mt][0][2], a[mt][0][3],
                      sIn + aoff + laneA[mt]);
                ldsm4(a[mt][1][0], a[mt][1][1], a[mt][1][2], a[mt][1][3],
                      sIn + (unsigned)(SIN_SP * 2) + aoff + laneA[mt]);
            }

            unsigned bf[8][2];
            // phase 1: B = w_hi (terms Ah*Bh, Al*Bh)
            {
                unsigned base = sW + woff + laneB;
#pragma unroll
                for (int j = 0; j < 4; j++)
                    ldsm4(bf[2 * j][0], bf[2 * j][1],
                          bf[2 * j + 1][0], bf[2 * j + 1][1],
                          base + (unsigned)(16 * j * 152) * 2u);
#pragma unroll
                for (int nf = 0; nf < 8; nf++)
#pragma unroll
                    for (int mt = 0; mt < 2; mt++) {
                        mma_bf16(acc[mt][nf], a[mt][0], bf[nf]);
                        mma_bf16(acc[mt][nf], a[mt][1], bf[nf]);
                    }
            }
            // phase 2: B = w_lo (term Ah*Bl)
            {
                unsigned base = sW + (unsigned)(W_SP * 2) + woff + laneB;
#pragma unroll
                for (int j = 0; j < 4; j++)
                    ldsm4(bf[2 * j][0], bf[2 * j][1],
                          bf[2 * j + 1][0], bf[2 * j + 1][1],
                          base + (unsigned)(16 * j * 152) * 2u);
#pragma unroll
                for (int nf = 0; nf < 8; nf++)
#pragma unroll
                    for (int mt = 0; mt < 2; mt++)
                        mma_bf16(acc[mt][nf], a[mt][0], bf[nf]);
            }
        }
    }

    // ---- fused LSTM epilogue ----
    const int c0    = (lane & 3) * 2;
    const int rbase = lane >> 2;
#pragma unroll
    for (int mt = 0; mt < 2; mt++) {
#pragma unroll
        for (int rr = 0; rr < 2; rr++) {
            const int pe = w * 32 + mt * 16 + rbase + 8 * rr;
            const int y  = y0 + (pe >> 6);
            const int x  = pe & 63;
#pragma unroll
            for (int q = 0; q < 4; q++) {
                const int hcl  = c0 + (q & 1) + ((q >> 1) << 3);
                const int off  = (hcl >= 8) ? 1 : 0;
                const int cidx = (hcl & 7) - c0 + rr * 2;
                float vi = acc[mt][0 + off][cidx];
                float vf = acc[mt][2 + off][cidx];
                float vo = acc[mt][4 + off][cidx];
                float vg = acc[mt][6 + off][cidx];
                float iv = 1.f / (1.f + __expf(-vi));
                float fv = 1.f / (1.f + __expf(-vf));
                float ov = 1.f / (1.f + __expf(-vo));
                float gv = tanhf(vg);
                const int hc = hcg * 16 + hcl;
                const size_t addr = (((size_t)b * 64 + hc) * 64 + y) * 64 + x;
                float cold = (t == 0) ? 0.f : cell_io[addr];
                float cnew = fv * cold + iv * gv;
                cell_io[addr] = cnew;
                float hval = ov * tanhf(cnew);
                if (last) {
                    hid_out[addr] = hval;
                } else {
                    __nv_bfloat16 hh = __float2bfloat16(hval);
                    g_hs[par_out][0][b][y][x][hc] = hh;
                    g_hs[par_out][1][b][y][x][hc] =
                        __float2bfloat16(hval - __bfloat162float(hh));
                }
            }
        }
    }
}

extern "C" void kernel_launch(void* const* d_in, const int* in_sizes, int n_in,
                              void* d_out, int out_size)
{
    const float* x  = (const float*)d_in[0];
    const float* Wk = (const float*)d_in[1];
    float* out  = (float*)d_out;
    float* hid  = out;
    float* cell = out + out_size / 2;

    cudaFuncSetAttribute(convlstm_mma,
                         cudaFuncAttributeMaxDynamicSharedMemorySize, SMEM_BYTES);

    prep_wpk<<<(4 * 8 * 19456 + 255) / 256, 256>>>(Wk);
    prep_x<<<8 * 16 * 64, 256>>>(x);

    dim3 grid(16, 4, 8), blk(256);
    for (int t = 0; t < 16; t++)
        convlstm_mma<<<grid, blk, SMEM_BYTES>>>(hid, cell, t, t == 15 ? 1 : 0);
}